// round 9
// baseline (speedup 1.0000x reference)
#include <cuda_runtime.h>
#include <cstdint>

// Problem constants
#define BB  8
#define NN_ 2048
#define DD  128
#define NH  8
#define NL  4
#define NCHUNK 16                    // gram split-K chunks (128 rows each)

#define SP   140                     // smem row stride: 140 % 32 == 12 -> all 4 fragment
                                     // patterns (12t+g, 12g+t) are bank-conflict-free
#define T64F (64 * SP)
#define T128F (128 * SP)
#define SM_GRAM (T128F * 4)          // 71680 B
#define SM_UPD  (2 * T128F * 4)      // 143360 B
#define SM_QG   ((T64F + T128F) * 4) // 107520 B

// Scratch
__device__ float g_Gp[NCHUNK * BB * DD * DD];  // gram partials (8.4MB)
__device__ float g_G[BB * DD * DD];            // reduced Gram
__device__ float g_M[BB * DD * DD];            // per-batch update matrix

// ---------------------------------------------------------------------------
__device__ __forceinline__ uint32_t tf32r(float f) {
    uint32_t u;
    asm("cvt.rna.tf32.f32 %0, %1;" : "=r"(u) : "f"(f));
    return u;
}

// Copy row-major [NR x 128] fp32 gmem tile -> smem [NR][SP], tf32-rounded.
template<int NR, int NT>
__device__ __forceinline__ void fill_tile(float* S, const float* __restrict__ g, int tid) {
    const float4* s4 = (const float4*)g;
#pragma unroll
    for (int it = 0; it < NR * 32 / NT; it++) {
        int i4 = it * NT + tid;
        int r = i4 >> 5;
        int c = (i4 & 31) * 4;
        float4 v = s4[i4];
        uint4 o;
        o.x = tf32r(v.x); o.y = tf32r(v.y); o.z = tf32r(v.z); o.w = tf32r(v.w);
        *(uint4*)(S + r * SP + c) = o;
    }
}

// Warp-level GEMM on mma.sync tf32. Warp tile = (MI*16) x 32 at (wm, wn).
// KS k-steps of 8. AT: A(m,k)=As[k][m]. BT: B(k,n)=Bs[n][k].
template<int MI, int KS, bool AT, bool BT>
__device__ __forceinline__ void wgemm(const float* A, const float* B,
                                      float (&acc)[MI][4][4], int wm, int wn, int lane) {
    const int g = lane >> 2, t = lane & 3;
    const uint32_t* Au = (const uint32_t*)A;
    const uint32_t* Bu = (const uint32_t*)B;
#pragma unroll 4
    for (int ks = 0; ks < KS; ks++) {
        const int k0 = ks * 8;
        uint32_t a[MI][4], b[4][2];
#pragma unroll
        for (int mi = 0; mi < MI; mi++) {
            const int m0 = wm + mi * 16;
            if (AT) {
                a[mi][0] = Au[(k0 + t) * SP + m0 + g];
                a[mi][1] = Au[(k0 + t) * SP + m0 + g + 8];
                a[mi][2] = Au[(k0 + t + 4) * SP + m0 + g];
                a[mi][3] = Au[(k0 + t + 4) * SP + m0 + g + 8];
            } else {
                a[mi][0] = Au[(m0 + g) * SP + k0 + t];
                a[mi][1] = Au[(m0 + g + 8) * SP + k0 + t];
                a[mi][2] = Au[(m0 + g) * SP + k0 + t + 4];
                a[mi][3] = Au[(m0 + g + 8) * SP + k0 + t + 4];
            }
        }
#pragma unroll
        for (int ni = 0; ni < 4; ni++) {
            const int n0 = wn + ni * 8;
            if (BT) {
                b[ni][0] = Bu[(n0 + g) * SP + k0 + t];
                b[ni][1] = Bu[(n0 + g) * SP + k0 + t + 4];
            } else {
                b[ni][0] = Bu[(k0 + t) * SP + n0 + g];
                b[ni][1] = Bu[(k0 + t + 4) * SP + n0 + g];
            }
        }
#pragma unroll
        for (int mi = 0; mi < MI; mi++)
#pragma unroll
            for (int ni = 0; ni < 4; ni++)
                asm("mma.sync.aligned.m16n8k8.row.col.f32.tf32.tf32.f32 "
                    "{%0,%1,%2,%3}, {%4,%5,%6,%7}, {%8,%9}, {%0,%1,%2,%3};"
                    : "+f"(acc[mi][ni][0]), "+f"(acc[mi][ni][1]),
                      "+f"(acc[mi][ni][2]), "+f"(acc[mi][ni][3])
                    : "r"(a[mi][0]), "r"(a[mi][1]), "r"(a[mi][2]), "r"(a[mi][3]),
                      "r"(b[ni][0]), "r"(b[ni][1]));
    }
}

#define ZERO_ACC(acc, MI) do { \
    _Pragma("unroll") for (int _i = 0; _i < (MI); _i++) \
    _Pragma("unroll") for (int _j = 0; _j < 4; _j++) \
    _Pragma("unroll") for (int _k = 0; _k < 4; _k++) acc[_i][_j][_k] = 0.0f; } while (0)

template<int MI>
__device__ __forceinline__ void store_part(float* P, float (&acc)[MI][4][4],
                                           int wm, int wn, int lane) {
    const int g = lane >> 2, t = lane & 3;
#pragma unroll
    for (int mi = 0; mi < MI; mi++)
#pragma unroll
        for (int ni = 0; ni < 4; ni++) {
            const int r = wm + mi * 16 + g, c = wn + ni * 8 + 2 * t;
            *(float2*)&P[(size_t)r * DD + c] =
                make_float2(acc[mi][ni][0], acc[mi][ni][1]);
            *(float2*)&P[(size_t)(r + 8) * DD + c] =
                make_float2(acc[mi][ni][2], acc[mi][ni][3]);
        }
}

// ---------------------------------------------------------------------------
// gram_part: partial Gram of input Z, chunk=128 rows. grid (16, B), 512 thr.
// (512, 1): full 128-reg budget -> no accumulator/fragment spills.
__global__ __launch_bounds__(512, 1) void gram_part(const float* __restrict__ Z) {
    extern __shared__ float smem[];
    const int b = blockIdx.y, s = blockIdx.x;
    const int tid = threadIdx.x, wid = tid >> 5, lane = tid & 31;

    fill_tile<128, 512>(smem, Z + ((size_t)b * NN_ + (size_t)s * 128) * DD, tid);
    __syncthreads();

    float acc[2][4][4];
    ZERO_ACC(acc, 2);
    const int wm = (wid >> 2) * 32, wn = (wid & 3) * 32;
    wgemm<2, 16, true, false>(smem, smem, acc, wm, wn, lane);

    store_part<2>(g_Gp + ((size_t)s * BB + b) * DD * DD, acc, wm, wn, lane);
}

// ---------------------------------------------------------------------------
// greduce: G[b] = sum_s Gp[s][b]; also zeroes M. grid 128, 256 thr (float4).
__global__ __launch_bounds__(256) void greduce() {
    const int idx = blockIdx.x * 256 + threadIdx.x;       // 0..32767 float4 units
    const int b = idx >> 12, i4 = idx & 4095;
    const float4* P = (const float4*)g_Gp;
    float4 s = make_float4(0.f, 0.f, 0.f, 0.f);
#pragma unroll
    for (int c = 0; c < NCHUNK; c++) {
        float4 v = P[((size_t)c * BB + b) * 4096 + i4];
        s.x += v.x; s.y += v.y; s.z += v.z; s.w += v.w;
    }
    ((float4*)g_G)[idx] = s;
    ((float4*)g_M)[idx] = make_float4(0.f, 0.f, 0.f, 0.f);
}

// ---------------------------------------------------------------------------
// qgtv: T = Q_j[rows] @ G_b; M[b][rows] += T @ V_j^T / (N*NH). grid (2, B*NH), 256 thr.
__global__ __launch_bounds__(256, 2) void qgtv(const float* __restrict__ Qm,
                                               const float* __restrict__ Vm) {
    extern __shared__ float smem[];
    float* bufA = smem;            // 64 x SP
    float* bufB = smem + T64F;     // 128 x SP
    const int half = blockIdx.x, bj = blockIdx.y, b = bj >> 3, j = bj & 7;
    const int tid = threadIdx.x, wid = tid >> 5, lane = tid & 31;
    const int g = lane >> 2, t = lane & 3;
    const int wm = (wid >> 2) * 32, wn = (wid & 3) * 32;

    fill_tile<64, 256>(bufA, Qm + (size_t)j * DD * DD + (size_t)half * 64 * DD, tid);
    fill_tile<128, 256>(bufB, g_G + (size_t)b * DD * DD, tid);
    __syncthreads();

    float acc[2][4][4];
    ZERO_ACC(acc, 2);
    wgemm<2, 16, false, false>(bufA, bufB, acc, wm, wn, lane);   // T = Q @ G
    __syncthreads();

    {   // T (tf32) into bufA; V into bufB
        uint32_t* Tu = (uint32_t*)bufA;
#pragma unroll
        for (int mi = 0; mi < 2; mi++)
#pragma unroll
            for (int ni = 0; ni < 4; ni++) {
                const int r = wm + mi * 16 + g, c = wn + ni * 8 + 2 * t;
                Tu[r * SP + c]           = tf32r(acc[mi][ni][0]);
                Tu[r * SP + c + 1]       = tf32r(acc[mi][ni][1]);
                Tu[(r + 8) * SP + c]     = tf32r(acc[mi][ni][2]);
                Tu[(r + 8) * SP + c + 1] = tf32r(acc[mi][ni][3]);
            }
        fill_tile<128, 256>(bufB, Vm + (size_t)j * DD * DD, tid);
    }
    __syncthreads();

    ZERO_ACC(acc, 2);
    wgemm<2, 16, false, true>(bufA, bufB, acc, wm, wn, lane);    // M_chunk = T @ V^T

    float* Mb = g_M + (size_t)b * DD * DD;
    const float S = 1.0f / ((float)NN_ * (float)NH);
#pragma unroll
    for (int mi = 0; mi < 2; mi++)
#pragma unroll
        for (int ni = 0; ni < 4; ni++) {
            const int r = half * 64 + wm + mi * 16 + g, c = wn + ni * 8 + 2 * t;
            atomicAdd(&Mb[(size_t)r * DD + c],           acc[mi][ni][0] * S);
            atomicAdd(&Mb[(size_t)r * DD + c + 1],       acc[mi][ni][1] * S);
            atomicAdd(&Mb[(size_t)(r + 8) * DD + c],     acc[mi][ni][2] * S);
            atomicAdd(&Mb[(size_t)(r + 8) * DD + c + 1], acc[mi][ni][3] * S);
        }
}

// ---------------------------------------------------------------------------
// update: Zout = Zin + Zin @ M[b] (128-row chunks, in-place safe), then (fused)
// writes next layer's Gram partial Zout^T @ Zout. grid (16, B), 512 thr.
// (512, 1): full 128-reg budget -> no accumulator/fragment spills.
__global__ __launch_bounds__(512, 1) void update(const float* __restrict__ Zin,
                                                 float* __restrict__ Zout, int do_gram) {
    extern __shared__ float smem[];
    float* bufA = smem;            // 128 x SP (Zin tile -> Zout tile)
    float* bufB = smem + T128F;    // 128 x SP (M)
    const int b = blockIdx.y, s = blockIdx.x;
    const int tid = threadIdx.x, wid = tid >> 5, lane = tid & 31;
    const int g = lane >> 2, t = lane & 3;
    const size_t zoff = ((size_t)b * NN_ + (size_t)s * 128) * DD;

    fill_tile<128, 512>(bufA, Zin + zoff, tid);
    fill_tile<128, 512>(bufB, g_M + (size_t)b * DD * DD, tid);
    __syncthreads();

    float acc[2][4][4];
    ZERO_ACC(acc, 2);
    const int wm = (wid >> 2) * 32, wn = (wid & 3) * 32;
    wgemm<2, 16, false, false>(bufA, bufB, acc, wm, wn, lane);
    __syncthreads();   // everyone done reading bufA

    // Epilogue: out = Zin + acc; stash tf32(Zout) in bufA for the gram phase.
    uint32_t* Au = (uint32_t*)bufA;
#pragma unroll
    for (int mi = 0; mi < 2; mi++)
#pragma unroll
        for (int ni = 0; ni < 4; ni++) {
            const int r = wm + mi * 16 + g, c = wn + ni * 8 + 2 * t;
            const float2 z0 = *(const float2*)&Zin[zoff + (size_t)r * DD + c];
            const float2 z1 = *(const float2*)&Zin[zoff + (size_t)(r + 8) * DD + c];
            float2 o0 = make_float2(z0.x + acc[mi][ni][0], z0.y + acc[mi][ni][1]);
            float2 o1 = make_float2(z1.x + acc[mi][ni][2], z1.y + acc[mi][ni][3]);
            *(float2*)&Zout[zoff + (size_t)r * DD + c]       = o0;
            *(float2*)&Zout[zoff + (size_t)(r + 8) * DD + c] = o1;
            Au[r * SP + c]           = tf32r(o0.x);
            Au[r * SP + c + 1]       = tf32r(o0.y);
            Au[(r + 8) * SP + c]     = tf32r(o1.x);
            Au[(r + 8) * SP + c + 1] = tf32r(o1.y);
        }

    if (!do_gram) return;
    __syncthreads();

    // Fused gram partial: Gp[s][b] = Zout_chunk^T @ Zout_chunk (K=128).
    float acc2[2][4][4];
    ZERO_ACC(acc2, 2);
    wgemm<2, 16, true, false>(bufA, bufA, acc2, wm, wn, lane);
    store_part<2>(g_Gp + ((size_t)s * BB + b) * DD * DD, acc2, wm, wn, lane);
}

// ---------------------------------------------------------------------------
extern "C" void kernel_launch(void* const* d_in, const int* in_sizes, int n_in,
                              void* d_out, int out_size) {
    const float* Z  = (const float*)d_in[0];
    const float* Vm = (const float*)d_in[1];  // [NL, NH, 1, D, D]
    const float* Qm = (const float*)d_in[2];  // [NL, NH, 1, D, D]
    float* out = (float*)d_out;

    cudaFuncSetAttribute(gram_part, cudaFuncAttributeMaxDynamicSharedMemorySize, SM_GRAM);
    cudaFuncSetAttribute(qgtv,      cudaFuncAttributeMaxDynamicSharedMemorySize, SM_QG);
    cudaFuncSetAttribute(update,    cudaFuncAttributeMaxDynamicSharedMemorySize, SM_UPD);

    gram_part<<<dim3(NCHUNK, BB), 512, SM_GRAM>>>(Z);
    for (int l = 0; l < NL; l++) {
        const float* Zin = (l == 0) ? Z : out;
        greduce<<<128, 256>>>();
        qgtv<<<dim3(2, BB * NH), 256, SM_QG>>>(Qm + (size_t)l * NH * DD * DD,
                                               Vm + (size_t)l * NH * DD * DD);
        update<<<dim3(NCHUNK, BB), 512, SM_UPD>>>(Zin, out, l < NL - 1);
    }
}

// round 11
// speedup vs baseline: 1.0314x; 1.0314x over previous
#include <cuda_runtime.h>
#include <cstdint>

// Problem constants
#define BB  8
#define NN_ 2048
#define DD  128
#define NH  8
#define NL  4
#define NCHUNK 16                    // gram split-K chunks (128 rows each)

#define SP   140                     // smem row stride: 140 % 32 == 12 -> all 4 fragment
                                     // patterns (12t+g, 12g+t) are bank-conflict-free
#define T64F (64 * SP)
#define T128F (128 * SP)
#define SM_GRAM (T128F * 4)          // 71680 B
#define SM_UPD  (2 * T128F * 4)      // 143360 B
#define SM_QG   ((T64F + T128F) * 4) // 107520 B

// Scratch
__device__ float g_Gp[NCHUNK * BB * DD * DD];  // gram partials (8.4MB)
__device__ float g_G[BB * DD * DD];            // reduced Gram
__device__ float g_M[BB * DD * DD];            // per-batch update matrix

// ---------------------------------------------------------------------------
__device__ __forceinline__ uint32_t tf32r(float f) {
    uint32_t u;
    asm("cvt.rna.tf32.f32 %0, %1;" : "=r"(u) : "f"(f));
    return u;
}

__device__ __forceinline__ void cp16(uint32_t s, const void* g) {
    asm volatile("cp.async.ca.shared.global [%0], [%1], 16;" :: "r"(s), "l"(g));
}
#define CP_WAIT_ALL() asm volatile("cp.async.wait_all;" ::: "memory")

// Async-copy a row-major [NR x 128] fp32 gmem tile -> smem [NR][SP].
// Raw fp32 bits: the tf32 MMA hardware truncates low mantissa bits itself.
template<int NR, int NT>
__device__ __forceinline__ void cp_fill(float* S, const float* __restrict__ g, int tid) {
    uint32_t sb = (uint32_t)__cvta_generic_to_shared(S);
#pragma unroll
    for (int it = 0; it < NR * 32 / NT; it++) {
        int i4 = it * NT + tid;
        int r = i4 >> 5, c = (i4 & 31) * 4;
        cp16(sb + (uint32_t)(r * SP + c) * 4u, (const char*)g + (size_t)i4 * 16);
    }
}

// ---------------------------------------------------------------------------
// Fragment load (one k-step of 8) and MMA issue, split for double-buffering.
template<int MI, bool AT, bool BT>
__device__ __forceinline__ void load_frag(uint32_t (&a)[MI][4], uint32_t (&b)[4][2],
                                          const uint32_t* Au, const uint32_t* Bu,
                                          int k0, int wm, int wn, int lane) {
    const int g = lane >> 2, t = lane & 3;
#pragma unroll
    for (int mi = 0; mi < MI; mi++) {
        const int m0 = wm + mi * 16;
        if (AT) {
            a[mi][0] = Au[(k0 + t) * SP + m0 + g];
            a[mi][1] = Au[(k0 + t) * SP + m0 + g + 8];
            a[mi][2] = Au[(k0 + t + 4) * SP + m0 + g];
            a[mi][3] = Au[(k0 + t + 4) * SP + m0 + g + 8];
        } else {
            a[mi][0] = Au[(m0 + g) * SP + k0 + t];
            a[mi][1] = Au[(m0 + g + 8) * SP + k0 + t];
            a[mi][2] = Au[(m0 + g) * SP + k0 + t + 4];
            a[mi][3] = Au[(m0 + g + 8) * SP + k0 + t + 4];
        }
    }
#pragma unroll
    for (int ni = 0; ni < 4; ni++) {
        const int n0 = wn + ni * 8;
        if (BT) {
            b[ni][0] = Bu[(n0 + g) * SP + k0 + t];
            b[ni][1] = Bu[(n0 + g) * SP + k0 + t + 4];
        } else {
            b[ni][0] = Bu[(k0 + t) * SP + n0 + g];
            b[ni][1] = Bu[(k0 + t + 4) * SP + n0 + g];
        }
    }
}

template<int MI>
__device__ __forceinline__ void mma_frag(float (&acc)[MI][4][4],
                                         const uint32_t (&a)[MI][4],
                                         const uint32_t (&b)[4][2]) {
#pragma unroll
    for (int mi = 0; mi < MI; mi++)
#pragma unroll
        for (int ni = 0; ni < 4; ni++)
            asm("mma.sync.aligned.m16n8k8.row.col.f32.tf32.tf32.f32 "
                "{%0,%1,%2,%3}, {%4,%5,%6,%7}, {%8,%9}, {%0,%1,%2,%3};"
                : "+f"(acc[mi][ni][0]), "+f"(acc[mi][ni][1]),
                  "+f"(acc[mi][ni][2]), "+f"(acc[mi][ni][3])
                : "r"(a[mi][0]), "r"(a[mi][1]), "r"(a[mi][2]), "r"(a[mi][3]),
                  "r"(b[ni][0]), "r"(b[ni][1]));
}

// Warp-level GEMM with explicit k-step fragment double-buffering.
template<int MI, int KS, bool AT, bool BT>
__device__ __forceinline__ void wgemm(const float* A, const float* B,
                                      float (&acc)[MI][4][4], int wm, int wn, int lane) {
    const uint32_t* Au = (const uint32_t*)A;
    const uint32_t* Bu = (const uint32_t*)B;
    uint32_t a0[MI][4], b0[4][2], a1[MI][4], b1[4][2];
    load_frag<MI, AT, BT>(a0, b0, Au, Bu, 0, wm, wn, lane);
#pragma unroll
    for (int ks = 0; ks < KS; ks += 2) {
        if (ks + 1 < KS) load_frag<MI, AT, BT>(a1, b1, Au, Bu, (ks + 1) * 8, wm, wn, lane);
        mma_frag<MI>(acc, a0, b0);
        if (ks + 2 < KS) load_frag<MI, AT, BT>(a0, b0, Au, Bu, (ks + 2) * 8, wm, wn, lane);
        if (ks + 1 < KS) mma_frag<MI>(acc, a1, b1);
    }
}

#define ZERO_ACC(acc, MI) do { \
    _Pragma("unroll") for (int _i = 0; _i < (MI); _i++) \
    _Pragma("unroll") for (int _j = 0; _j < 4; _j++) \
    _Pragma("unroll") for (int _k = 0; _k < 4; _k++) acc[_i][_j][_k] = 0.0f; } while (0)

template<int MI>
__device__ __forceinline__ void store_part(float* P, float (&acc)[MI][4][4],
                                           int wm, int wn, int lane) {
    const int g = lane >> 2, t = lane & 3;
#pragma unroll
    for (int mi = 0; mi < MI; mi++)
#pragma unroll
        for (int ni = 0; ni < 4; ni++) {
            const int r = wm + mi * 16 + g, c = wn + ni * 8 + 2 * t;
            *(float2*)&P[(size_t)r * DD + c] =
                make_float2(acc[mi][ni][0], acc[mi][ni][1]);
            *(float2*)&P[(size_t)(r + 8) * DD + c] =
                make_float2(acc[mi][ni][2], acc[mi][ni][3]);
        }
}

// ---------------------------------------------------------------------------
// gram_part: partial Gram of input Z, chunk=128 rows. grid (16, B), 512 thr.
__global__ __launch_bounds__(512, 1) void gram_part(const float* __restrict__ Z) {
    extern __shared__ float smem[];
    const int b = blockIdx.y, s = blockIdx.x;
    const int tid = threadIdx.x, wid = tid >> 5, lane = tid & 31;

    cp_fill<128, 512>(smem, Z + ((size_t)b * NN_ + (size_t)s * 128) * DD, tid);
    CP_WAIT_ALL();
    __syncthreads();

    float acc[2][4][4];
    ZERO_ACC(acc, 2);
    const int wm = (wid >> 2) * 32, wn = (wid & 3) * 32;
    wgemm<2, 16, true, false>(smem, smem, acc, wm, wn, lane);

    store_part<2>(g_Gp + ((size_t)s * BB + b) * DD * DD, acc, wm, wn, lane);
}

// ---------------------------------------------------------------------------
// greduce: G[b] = sum_s Gp[s][b]; also zeroes M. grid 128, 256 thr (float4).
__global__ __launch_bounds__(256) void greduce() {
    const int idx = blockIdx.x * 256 + threadIdx.x;       // 0..32767 float4 units
    const int b = idx >> 12, i4 = idx & 4095;
    const float4* P = (const float4*)g_Gp;
    float4 s = make_float4(0.f, 0.f, 0.f, 0.f);
#pragma unroll
    for (int c = 0; c < NCHUNK; c++) {
        float4 v = P[((size_t)c * BB + b) * 4096 + i4];
        s.x += v.x; s.y += v.y; s.z += v.z; s.w += v.w;
    }
    ((float4*)g_G)[idx] = s;
    ((float4*)g_M)[idx] = make_float4(0.f, 0.f, 0.f, 0.f);
}

// ---------------------------------------------------------------------------
// qgtv: T = Q_j[rows] @ G_b; M[b][rows] += T @ V_j^T / (N*NH). grid (2, B*NH), 256 thr.
__global__ __launch_bounds__(256, 2) void qgtv(const float* __restrict__ Qm,
                                               const float* __restrict__ Vm) {
    extern __shared__ float smem[];
    float* bufA = smem;            // 64 x SP
    float* bufB = smem + T64F;     // 128 x SP
    const int half = blockIdx.x, bj = blockIdx.y, b = bj >> 3, j = bj & 7;
    const int tid = threadIdx.x, wid = tid >> 5, lane = tid & 31;
    const int g = lane >> 2, t = lane & 3;
    const int wm = (wid >> 2) * 32, wn = (wid & 3) * 32;

    cp_fill<64, 256>(bufA, Qm + (size_t)j * DD * DD + (size_t)half * 64 * DD, tid);
    cp_fill<128, 256>(bufB, g_G + (size_t)b * DD * DD, tid);
    CP_WAIT_ALL();
    __syncthreads();

    float acc[2][4][4];
    ZERO_ACC(acc, 2);
    wgemm<2, 16, false, false>(bufA, bufB, acc, wm, wn, lane);   // T = Q @ G
    __syncthreads();

    {   // T (tf32) into bufA; V into bufB (async)
        cp_fill<128, 256>(bufB, Vm + (size_t)j * DD * DD, tid);
        uint32_t* Tu = (uint32_t*)bufA;
#pragma unroll
        for (int mi = 0; mi < 2; mi++)
#pragma unroll
            for (int ni = 0; ni < 4; ni++) {
                const int r = wm + mi * 16 + g, c = wn + ni * 8 + 2 * t;
                Tu[r * SP + c]           = tf32r(acc[mi][ni][0]);
                Tu[r * SP + c + 1]       = tf32r(acc[mi][ni][1]);
                Tu[(r + 8) * SP + c]     = tf32r(acc[mi][ni][2]);
                Tu[(r + 8) * SP + c + 1] = tf32r(acc[mi][ni][3]);
            }
        CP_WAIT_ALL();
    }
    __syncthreads();

    ZERO_ACC(acc, 2);
    wgemm<2, 16, false, true>(bufA, bufB, acc, wm, wn, lane);    // M_chunk = T @ V^T

    float* Mb = g_M + (size_t)b * DD * DD;
    const float S = 1.0f / ((float)NN_ * (float)NH);
#pragma unroll
    for (int mi = 0; mi < 2; mi++)
#pragma unroll
        for (int ni = 0; ni < 4; ni++) {
            const int r = half * 64 + wm + mi * 16 + g, c = wn + ni * 8 + 2 * t;
            atomicAdd(&Mb[(size_t)r * DD + c],           acc[mi][ni][0] * S);
            atomicAdd(&Mb[(size_t)r * DD + c + 1],       acc[mi][ni][1] * S);
            atomicAdd(&Mb[(size_t)(r + 8) * DD + c],     acc[mi][ni][2] * S);
            atomicAdd(&Mb[(size_t)(r + 8) * DD + c + 1], acc[mi][ni][3] * S);
        }
}

// ---------------------------------------------------------------------------
// update: Zout = Zin + Zin @ M[b] (128-row chunks, in-place safe), then (fused)
// writes next layer's Gram partial Zout^T @ Zout. grid (16, B), 512 thr.
__global__ __launch_bounds__(512, 1) void update(const float* __restrict__ Zin,
                                                 float* __restrict__ Zout, int do_gram) {
    extern __shared__ float smem[];
    float* bufA = smem;            // 128 x SP (Zin tile -> Zout tile)
    float* bufB = smem + T128F;    // 128 x SP (M)
    const int b = blockIdx.y, s = blockIdx.x;
    const int tid = threadIdx.x, wid = tid >> 5, lane = tid & 31;
    const int g = lane >> 2, t = lane & 3;
    const size_t zoff = ((size_t)b * NN_ + (size_t)s * 128) * DD;

    cp_fill<128, 512>(bufA, Zin + zoff, tid);
    cp_fill<128, 512>(bufB, g_M + (size_t)b * DD * DD, tid);
    CP_WAIT_ALL();
    __syncthreads();

    float acc[2][4][4];
    ZERO_ACC(acc, 2);
    const int wm = (wid >> 2) * 32, wn = (wid & 3) * 32;
    wgemm<2, 16, false, false>(bufA, bufB, acc, wm, wn, lane);
    __syncthreads();   // everyone done reading bufA

    // Epilogue: out = Zin + acc; stash tf32(Zout) in bufA for the gram phase.
    uint32_t* Au = (uint32_t*)bufA;
#pragma unroll
    for (int mi = 0; mi < 2; mi++)
#pragma unroll
        for (int ni = 0; ni < 4; ni++) {
            const int r = wm + mi * 16 + g, c = wn + ni * 8 + 2 * t;
            const float2 z0 = *(const float2*)&Zin[zoff + (size_t)r * DD + c];
            const float2 z1 = *(const float2*)&Zin[zoff + (size_t)(r + 8) * DD + c];
            float2 o0 = make_float2(z0.x + acc[mi][ni][0], z0.y + acc[mi][ni][1]);
            float2 o1 = make_float2(z1.x + acc[mi][ni][2], z1.y + acc[mi][ni][3]);
            *(float2*)&Zout[zoff + (size_t)r * DD + c]       = o0;
            *(float2*)&Zout[zoff + (size_t)(r + 8) * DD + c] = o1;
            Au[r * SP + c]           = tf32r(o0.x);
            Au[r * SP + c + 1]       = tf32r(o0.y);
            Au[(r + 8) * SP + c]     = tf32r(o1.x);
            Au[(r + 8) * SP + c + 1] = tf32r(o1.y);
        }

    if (!do_gram) return;
    __syncthreads();

    // Fused gram partial: Gp[s][b] = Zout_chunk^T @ Zout_chunk (K=128).
    float acc2[2][4][4];
    ZERO_ACC(acc2, 2);
    wgemm<2, 16, true, false>(bufA, bufA, acc2, wm, wn, lane);
    store_part<2>(g_Gp + ((size_t)s * BB + b) * DD * DD, acc2, wm, wn, lane);
}

// ---------------------------------------------------------------------------
extern "C" void kernel_launch(void* const* d_in, const int* in_sizes, int n_in,
                              void* d_out, int out_size) {
    const float* Z  = (const float*)d_in[0];
    const float* Vm = (const float*)d_in[1];  // [NL, NH, 1, D, D]
    const float* Qm = (const float*)d_in[2];  // [NL, NH, 1, D, D]
    float* out = (float*)d_out;

    cudaFuncSetAttribute(gram_part, cudaFuncAttributeMaxDynamicSharedMemorySize, SM_GRAM);
    cudaFuncSetAttribute(qgtv,      cudaFuncAttributeMaxDynamicSharedMemorySize, SM_QG);
    cudaFuncSetAttribute(update,    cudaFuncAttributeMaxDynamicSharedMemorySize, SM_UPD);

    gram_part<<<dim3(NCHUNK, BB), 512, SM_GRAM>>>(Z);
    for (int l = 0; l < NL; l++) {
        const float* Zin = (l == 0) ? Z : out;
        greduce<<<128, 256>>>();
        qgtv<<<dim3(2, BB * NH), 256, SM_QG>>>(Qm + (size_t)l * NH * DD * DD,
                                               Vm + (size_t)l * NH * DD * DD);
        update<<<dim3(NCHUNK, BB), 512, SM_UPD>>>(Zin, out, l < NL - 1);
    }
}

// round 14
// speedup vs baseline: 1.4581x; 1.4137x over previous
#include <cuda_runtime.h>
#include <cuda_fp16.h>
#include <cstdint>

// Problem constants
#define BB  8
#define NN_ 2048
#define DD  128
#define NH  8
#define NL  4
#define NCHUNK 16                    // gram split-K chunks (128 rows each)

// f16 tiles: row stride SPH uint32 (=136 halves, 128 used). SPH%32==4 ->
// fragment pattern banks (4g+t) are conflict-free for ALL operand loads.
#define SPH 68
#define T64U  (64 * SPH)
#define T128U (128 * SPH)
#define SM_GRAM (T128U * 4)              // 34816 B
#define SM_QG   ((T64U + T128U) * 4)     // 52224 B
#define SM_UPD  (3 * T128U * 4)          // 104448 B

// Scratch
__device__ float g_Gp[NCHUNK * BB * DD * DD];  // gram partials (8.4MB, f32)
__device__ float g_G[BB * DD * DD];            // reduced Gram (f32)
__device__ float g_Mt[BB * DD * DD];           // Mt[n][k] = M[k][n]  (f32)

// ---------------------------------------------------------------------------
__device__ __forceinline__ uint32_t pack2(float lo, float hi) {
    __half2 h = __floats2half2_rn(lo, hi);     // lo -> low 16 bits
    return *reinterpret_cast<uint32_t*>(&h);
}

// f32 gmem row-major [NR x 128] -> f16 smem tile [NR][SPH] (k-contiguous rows).
template<int NR, int NT>
__device__ __forceinline__ void cvt_fill(uint32_t* S, const float* __restrict__ g, int tid) {
    const float4* s4 = (const float4*)g;
#pragma unroll
    for (int it = 0; it < NR * 32 / NT; it++) {
        int i4 = it * NT + tid;
        int r = i4 >> 5, c4 = i4 & 31;         // c4: which float4 (=2 uint32 of halves)
        float4 v = s4[i4];
        uint2 o = make_uint2(pack2(v.x, v.y), pack2(v.z, v.w));
        *(uint2*)(S + r * SPH + c4 * 2) = o;
    }
}

// f32 gmem row-major [128 x 128] -> TRANSPOSED f16 smem tile: S[c][r] = g[r][c].
template<int NT>
__device__ __forceinline__ void cvt_fill_T(uint32_t* S, const float* __restrict__ g, int tid) {
    __half* H = (__half*)S;
    const float4* s4 = (const float4*)g;
#pragma unroll
    for (int it = 0; it < 128 * 32 / NT; it++) {
        int i4 = it * NT + tid;
        int r = i4 >> 5, c = (i4 & 31) * 4;
        float4 v = s4[i4];
        H[(c + 0) * (2 * SPH) + r] = __float2half_rn(v.x);
        H[(c + 1) * (2 * SPH) + r] = __float2half_rn(v.y);
        H[(c + 2) * (2 * SPH) + r] = __float2half_rn(v.z);
        H[(c + 3) * (2 * SPH) + r] = __float2half_rn(v.w);
    }
}

// ---------------------------------------------------------------------------
// f16 m16n8k16 fragments. A tile: As[m][k], B tile: Bs[n][k] (both k-contig).
// kk = k-step * 8 (uint32 units; 16 halves per step).
template<int MI>
__device__ __forceinline__ void load_frag_h(uint32_t (&a)[MI][4], uint32_t (&b)[4][2],
                                            const uint32_t* Au, const uint32_t* Bu,
                                            int kk, int wm, int wn, int lane) {
    const int g = lane >> 2, t = lane & 3;
#pragma unroll
    for (int mi = 0; mi < MI; mi++) {
        const int m0 = wm + mi * 16;
        a[mi][0] = Au[(m0 + g) * SPH + kk + t];
        a[mi][1] = Au[(m0 + g + 8) * SPH + kk + t];
        a[mi][2] = Au[(m0 + g) * SPH + kk + t + 4];
        a[mi][3] = Au[(m0 + g + 8) * SPH + kk + t + 4];
    }
#pragma unroll
    for (int ni = 0; ni < 4; ni++) {
        const int n0 = wn + ni * 8;
        b[ni][0] = Bu[(n0 + g) * SPH + kk + t];
        b[ni][1] = Bu[(n0 + g) * SPH + kk + t + 4];
    }
}

template<int MI>
__device__ __forceinline__ void mma_frag_h(float (&acc)[MI][4][4],
                                           const uint32_t (&a)[MI][4],
                                           const uint32_t (&b)[4][2]) {
#pragma unroll
    for (int mi = 0; mi < MI; mi++)
#pragma unroll
        for (int ni = 0; ni < 4; ni++)
            asm("mma.sync.aligned.m16n8k16.row.col.f32.f16.f16.f32 "
                "{%0,%1,%2,%3}, {%4,%5,%6,%7}, {%8,%9}, {%0,%1,%2,%3};"
                : "+f"(acc[mi][ni][0]), "+f"(acc[mi][ni][1]),
                  "+f"(acc[mi][ni][2]), "+f"(acc[mi][ni][3])
                : "r"(a[mi][0]), "r"(a[mi][1]), "r"(a[mi][2]), "r"(a[mi][3]),
                  "r"(b[ni][0]), "r"(b[ni][1]));
}

// K=128 GEMM = 8 k16-steps, fragment double-buffered.
template<int MI>
__device__ __forceinline__ void wgemm_h(const uint32_t* Au, const uint32_t* Bu,
                                        float (&acc)[MI][4][4], int wm, int wn, int lane) {
    uint32_t a0[MI][4], b0[4][2], a1[MI][4], b1[4][2];
    load_frag_h<MI>(a0, b0, Au, Bu, 0, wm, wn, lane);
#pragma unroll
    for (int ks = 0; ks < 8; ks += 2) {
        if (ks + 1 < 8) load_frag_h<MI>(a1, b1, Au, Bu, (ks + 1) * 8, wm, wn, lane);
        mma_frag_h<MI>(acc, a0, b0);
        if (ks + 2 < 8) load_frag_h<MI>(a0, b0, Au, Bu, (ks + 2) * 8, wm, wn, lane);
        if (ks + 1 < 8) mma_frag_h<MI>(acc, a1, b1);
    }
}

#define ZERO_ACC(acc, MI) do { \
    _Pragma("unroll") for (int _i = 0; _i < (MI); _i++) \
    _Pragma("unroll") for (int _j = 0; _j < 4; _j++) \
    _Pragma("unroll") for (int _k = 0; _k < 4; _k++) acc[_i][_j][_k] = 0.0f; } while (0)

template<int MI>
__device__ __forceinline__ void store_part(float* P, float (&acc)[MI][4][4],
                                           int wm, int wn, int lane) {
    const int g = lane >> 2, t = lane & 3;
#pragma unroll
    for (int mi = 0; mi < MI; mi++)
#pragma unroll
        for (int ni = 0; ni < 4; ni++) {
            const int r = wm + mi * 16 + g, c = wn + ni * 8 + 2 * t;
            *(float2*)&P[(size_t)r * DD + c] =
                make_float2(acc[mi][ni][0], acc[mi][ni][1]);
            *(float2*)&P[(size_t)(r + 8) * DD + c] =
                make_float2(acc[mi][ni][2], acc[mi][ni][3]);
        }
}

// ---------------------------------------------------------------------------
// gram_part: Gp[s][b] = Zc^T @ Zc (128-row chunk). grid (16, B), 512 thr.
// One TRANSPOSED f16 tile serves as both A (As[m][k]=Z[k][m]) and B (Bs[n][k]=Z[k][n]).
__global__ __launch_bounds__(512, 1) void gram_part(const float* __restrict__ Z) {
    extern __shared__ uint32_t smem[];
    const int b = blockIdx.y, s = blockIdx.x;
    const int tid = threadIdx.x, wid = tid >> 5, lane = tid & 31;

    cvt_fill_T<512>(smem, Z + ((size_t)b * NN_ + (size_t)s * 128) * DD, tid);
    __syncthreads();

    float acc[2][4][4];
    ZERO_ACC(acc, 2);
    const int wm = (wid >> 2) * 32, wn = (wid & 3) * 32;
    wgemm_h<2>(smem, smem, acc, wm, wn, lane);

    store_part<2>(g_Gp + ((size_t)s * BB + b) * DD * DD, acc, wm, wn, lane);
}

// ---------------------------------------------------------------------------
// greduce: G[b] = sum_s Gp[s][b]; zeroes Mt. grid 128, 256 thr (float4).
__global__ __launch_bounds__(256) void greduce() {
    const int idx = blockIdx.x * 256 + threadIdx.x;
    const int b = idx >> 12, i4 = idx & 4095;
    const float4* P = (const float4*)g_Gp;
    float4 s = make_float4(0.f, 0.f, 0.f, 0.f);
#pragma unroll
    for (int c = 0; c < NCHUNK; c++) {
        float4 v = P[((size_t)c * BB + b) * 4096 + i4];
        s.x += v.x; s.y += v.y; s.z += v.z; s.w += v.w;
    }
    ((float4*)g_G)[idx] = s;
    ((float4*)g_Mt)[idx] = make_float4(0.f, 0.f, 0.f, 0.f);
}

// ---------------------------------------------------------------------------
// qgtv: T = Q_j[64 rows] @ G_b; Mt[b] += (T @ V_j^T)^T / (N*NH).
// grid (2, B*NH), 256 thr. B operands: G symmetric; V natural [n][k].
__global__ __launch_bounds__(256, 2) void qgtv(const float* __restrict__ Qm,
                                               const float* __restrict__ Vm) {
    extern __shared__ uint32_t smem[];
    uint32_t* bufA = smem;           // 64 x SPH  (Q, then T)
    uint32_t* bufB = smem + T64U;    // 128 x SPH (G, then V)
    const int half = blockIdx.x, bj = blockIdx.y, b = bj >> 3, j = bj & 7;
    const int tid = threadIdx.x, wid = tid >> 5, lane = tid & 31;
    const int g = lane >> 2, t = lane & 3;
    const int wm = (wid >> 2) * 32, wn = (wid & 3) * 32;

    cvt_fill<64, 256>(bufA, Qm + (size_t)j * DD * DD + (size_t)half * 64 * DD, tid);
    cvt_fill<128, 256>(bufB, g_G + (size_t)b * DD * DD, tid);
    __syncthreads();

    float acc[2][4][4];
    ZERO_ACC(acc, 2);
    wgemm_h<2>(bufA, bufB, acc, wm, wn, lane);       // T = Q @ G  (Bs[n][k]=G[n][k], sym)
    __syncthreads();

    {   // T (f16 pairs) into bufA; V into bufB
#pragma unroll
        for (int mi = 0; mi < 2; mi++)
#pragma unroll
            for (int ni = 0; ni < 4; ni++) {
                const int r = wm + mi * 16 + g, c = wn + ni * 8 + 2 * t;
                bufA[r * SPH + (c >> 1)]       = pack2(acc[mi][ni][0], acc[mi][ni][1]);
                bufA[(r + 8) * SPH + (c >> 1)] = pack2(acc[mi][ni][2], acc[mi][ni][3]);
            }
        cvt_fill<128, 256>(bufB, Vm + (size_t)j * DD * DD, tid);
    }
    __syncthreads();

    ZERO_ACC(acc, 2);
    wgemm_h<2>(bufA, bufB, acc, wm, wn, lane);       // M = T @ V^T (Bs[n][k]=V[n][k])

    float* Mb = g_Mt + (size_t)b * DD * DD;          // Mt[n][k]
    const float S = 1.0f / ((float)NN_ * (float)NH);
#pragma unroll
    for (int mi = 0; mi < 2; mi++)
#pragma unroll
        for (int ni = 0; ni < 4; ni++) {
            const int r = half * 64 + wm + mi * 16 + g, c = wn + ni * 8 + 2 * t;
            atomicAdd(&Mb[(size_t)c * DD + r],           acc[mi][ni][0] * S);
            atomicAdd(&Mb[(size_t)(c + 1) * DD + r],     acc[mi][ni][1] * S);
            atomicAdd(&Mb[(size_t)c * DD + r + 8],       acc[mi][ni][2] * S);
            atomicAdd(&Mb[(size_t)(c + 1) * DD + r + 8], acc[mi][ni][3] * S);
        }
}

// ---------------------------------------------------------------------------
// update: Zout = Zin + Zin @ M[b] (128-row chunks, in-place safe), then fused
// next-layer Gram partial from a transposed f16 Zout tile. grid (16, B), 512 thr.
__global__ __launch_bounds__(512, 1) void update(const float* __restrict__ Zin,
                                                 float* __restrict__ Zout, int do_gram) {
    extern __shared__ uint32_t smem[];
    uint32_t* bufA = smem;             // Zin f16 [128][SPH]
    uint32_t* bufB = smem + T128U;     // Mt  f16 (Bs[n][k] = M[k][n])
    uint32_t* bufC = smem + 2 * T128U; // ZoutT f16 (for gram)
    const int b = blockIdx.y, s = blockIdx.x;
    const int tid = threadIdx.x, wid = tid >> 5, lane = tid & 31;
    const int g = lane >> 2, t = lane & 3;
    const size_t zoff = ((size_t)b * NN_ + (size_t)s * 128) * DD;

    cvt_fill<128, 512>(bufA, Zin + zoff, tid);
    cvt_fill<128, 512>(bufB, g_Mt + (size_t)b * DD * DD, tid);
    __syncthreads();

    float acc[2][4][4];
    ZERO_ACC(acc, 2);
    const int wm = (wid >> 2) * 32, wn = (wid & 3) * 32;
    wgemm_h<2>(bufA, bufB, acc, wm, wn, lane);

    // Epilogue: out = Zin(f32) + acc; stash f16 Zout TRANSPOSED into bufC.
    __half* HC = (__half*)bufC;
#pragma unroll
    for (int mi = 0; mi < 2; mi++)
#pragma unroll
        for (int ni = 0; ni < 4; ni++) {
            const int r = wm + mi * 16 + g, c = wn + ni * 8 + 2 * t;
            const float2 z0 = *(const float2*)&Zin[zoff + (size_t)r * DD + c];
            const float2 z1 = *(const float2*)&Zin[zoff + (size_t)(r + 8) * DD + c];
            float2 o0 = make_float2(z0.x + acc[mi][ni][0], z0.y + acc[mi][ni][1]);
            float2 o1 = make_float2(z1.x + acc[mi][ni][2], z1.y + acc[mi][ni][3]);
            *(float2*)&Zout[zoff + (size_t)r * DD + c]       = o0;
            *(float2*)&Zout[zoff + (size_t)(r + 8) * DD + c] = o1;
            if (do_gram) {
                HC[c * (2 * SPH) + r]           = __float2half_rn(o0.x);
                HC[(c + 1) * (2 * SPH) + r]     = __float2half_rn(o0.y);
                HC[c * (2 * SPH) + r + 8]       = __float2half_rn(o1.x);
                HC[(c + 1) * (2 * SPH) + r + 8] = __float2half_rn(o1.y);
            }
        }

    if (!do_gram) return;
    __syncthreads();

    // Fused gram partial: Gp[s][b] = Zout^T @ Zout, both operands = bufC.
    float acc2[2][4][4];
    ZERO_ACC(acc2, 2);
    wgemm_h<2>(bufC, bufC, acc2, wm, wn, lane);
    store_part<2>(g_Gp + ((size_t)s * BB + b) * DD * DD, acc2, wm, wn, lane);
}

// ---------------------------------------------------------------------------
extern "C" void kernel_launch(void* const* d_in, const int* in_sizes, int n_in,
                              void* d_out, int out_size) {
    const float* Z  = (const float*)d_in[0];
    const float* Vm = (const float*)d_in[1];  // [NL, NH, 1, D, D]
    const float* Qm = (const float*)d_in[2];  // [NL, NH, 1, D, D]
    float* out = (float*)d_out;

    cudaFuncSetAttribute(gram_part, cudaFuncAttributeMaxDynamicSharedMemorySize, SM_GRAM);
    cudaFuncSetAttribute(qgtv,      cudaFuncAttributeMaxDynamicSharedMemorySize, SM_QG);
    cudaFuncSetAttribute(update,    cudaFuncAttributeMaxDynamicSharedMemorySize, SM_UPD);

    gram_part<<<dim3(NCHUNK, BB), 512, SM_GRAM>>>(Z);
    for (int l = 0; l < NL; l++) {
        const float* Zin = (l == 0) ? Z : out;
        greduce<<<128, 256>>>();
        qgtv<<<dim3(2, BB * NH), 256, SM_QG>>>(Qm + (size_t)l * NH * DD * DD,
                                               Vm + (size_t)l * NH * DD * DD);
        update<<<dim3(NCHUNK, BB), 512, SM_UPD>>>(Zin, out, l < NL - 1);
    }
}